// round 1
// baseline (speedup 1.0000x reference)
#include <cuda_runtime.h>
#include <math.h>

#define BB 2048
#define LL 200
#define DD 128
#define H0N 80
#define H1N 40

// shared memory layout (floats)
#define OFF_HIST   0                       // [200][129]  = 25800
#define OFF_A0     (OFF_HIST + 200*129)    // [128][80]   = 10240
#define OFF_H0     (OFF_A0 + 128*80)       // [200][81]   = 16200
#define OFF_W1     (OFF_H0 + 200*81)       // [80][40]    = 3200
#define OFF_TGT    (OFF_W1 + 3200)         // 128
#define OFF_C0     (OFF_TGT + 128)         // 80
#define OFF_B1     (OFF_C0 + 80)           // 40
#define OFF_W2     (OFF_B1 + 40)           // 40
#define OFF_ATTN   (OFF_W2 + 40)           // 200
#define OFF_RED    (OFF_ATTN + 200)        // 32
#define SMEM_FLOATS (OFF_RED + 32)

__global__ __launch_bounds__(256, 1)
void din_kernel(const float* __restrict__ hist,
                const float* __restrict__ tgt,
                const int*   __restrict__ mask,
                const float* __restrict__ W0,
                const float* __restrict__ b0,
                const float* __restrict__ W1,
                const float* __restrict__ b1,
                const float* __restrict__ W2,
                const float* __restrict__ b2,
                float* __restrict__ out)
{
    extern __shared__ float sm[];
    float* histS = sm + OFF_HIST;
    float* A0s   = sm + OFF_A0;
    float* h0S   = sm + OFF_H0;
    float* W1s   = sm + OFF_W1;
    float* tgtS  = sm + OFF_TGT;
    float* c0s   = sm + OFF_C0;
    float* b1s   = sm + OFF_B1;
    float* w2s   = sm + OFF_W2;
    float* attnS = sm + OFF_ATTN;
    float* redS  = sm + OFF_RED;

    const int b   = blockIdx.x;
    const int tid = threadIdx.x;

    // ---- target vector ----
    if (tid < DD) tgtS[tid] = tgt[(size_t)b * DD + tid];
    __syncthreads();

    // ---- stage hist[b] into smem (padded rows of 129) ----
    {
        const float4* hb = (const float4*)(hist + (size_t)b * LL * DD);
        #pragma unroll
        for (int it = 0; it < 25; ++it) {
            int idx = tid + it * 256;              // 0 .. 6399
            float4 v = hb[idx];
            int l  = idx >> 5;                     // idx / 32
            int d4 = (idx & 31) << 2;
            float* r = &histS[l * 129 + d4];
            r[0] = v.x; r[1] = v.y; r[2] = v.z; r[3] = v.w;
        }
    }

    // ---- build per-batch effective layer-0 weights:
    //  A0[d][h] = W0_hist[d][h] + W0_diff[d][h] + tgt[d]*W0_prod[d][h]
    for (int idx = tid; idx < DD * H0N; idx += 256) {
        int d = idx / H0N;
        int h = idx - d * H0N;
        A0s[idx] = W0[d * H0N + h]
                 + W0[(2 * DD + d) * H0N + h]
                 + tgtS[d] * W0[(3 * DD + d) * H0N + h];
    }
    //  c0[h] = b0[h] + sum_d tgt[d]*(W0_tgt[d][h] - W0_diff[d][h])
    if (tid < H0N) {
        float s = b0[tid];
        #pragma unroll 4
        for (int d = 0; d < DD; ++d)
            s += tgtS[d] * (W0[(DD + d) * H0N + tid] - W0[(2 * DD + d) * H0N + tid]);
        c0s[tid] = s;
    }
    // small weights
    for (int idx = tid; idx < H0N * H1N; idx += 256) W1s[idx] = W1[idx];
    if (tid < H1N) { b1s[tid] = b1[tid]; w2s[tid] = W2[tid]; }
    __syncthreads();

    // ---- layer 0 GEMM: h0[200][80] = relu(hist @ A0 + c0) ----
    // 250 threads; each computes an 8(l) x 8(h) register tile
    if (tid < 250) {
        const int lt = tid / 10;
        const int ht = tid - lt * 10;
        const int l0 = lt * 8;
        const int h0 = ht * 8;
        float acc[8][8];
        #pragma unroll
        for (int i = 0; i < 8; ++i)
            #pragma unroll
            for (int j = 0; j < 8; ++j) acc[i][j] = 0.f;

        #pragma unroll 2
        for (int d = 0; d < DD; ++d) {
            float a[8], w[8];
            #pragma unroll
            for (int i = 0; i < 8; ++i) a[i] = histS[(l0 + i) * 129 + d];
            #pragma unroll
            for (int j = 0; j < 8; ++j) w[j] = A0s[d * H0N + h0 + j];
            #pragma unroll
            for (int i = 0; i < 8; ++i)
                #pragma unroll
                for (int j = 0; j < 8; ++j)
                    acc[i][j] = fmaf(a[i], w[j], acc[i][j]);
        }
        #pragma unroll
        for (int i = 0; i < 8; ++i)
            #pragma unroll
            for (int j = 0; j < 8; ++j) {
                float v = acc[i][j] + c0s[h0 + j];
                h0S[(l0 + i) * 81 + h0 + j] = v > 0.f ? v : 0.f;
            }
    }
    __syncthreads();

    // ---- layers 1+2 fused, per-l in one thread; h0 row cached in regs ----
    float logit = -3.402823466e38f;
    if (tid < LL) {
        float hr[H0N];
        #pragma unroll
        for (int k = 0; k < H0N; ++k) hr[k] = h0S[tid * 81 + k];
        float score = b2[0];
        #pragma unroll 1
        for (int j = 0; j < H1N; ++j) {
            float s = b1s[j];
            #pragma unroll
            for (int k = 0; k < H0N; ++k)
                s = fmaf(hr[k], W1s[k * H1N + j], s);
            s = fmaxf(s, 0.f);
            score = fmaf(s, w2s[j], score);
        }
        float m = (float)mask[(size_t)b * LL + tid];
        logit = score + (1.0f - m) * (-1e9f);
    }

    // ---- masked softmax over L (shuffle + smem reduction) ----
    {
        float v = logit;
        #pragma unroll
        for (int o = 16; o; o >>= 1) v = fmaxf(v, __shfl_xor_sync(0xffffffffu, v, o));
        if ((tid & 31) == 0) redS[tid >> 5] = v;
    }
    __syncthreads();
    if (tid < 32) {
        float m = (tid < 8) ? redS[tid] : -3.402823466e38f;
        #pragma unroll
        for (int o = 4; o; o >>= 1) m = fmaxf(m, __shfl_xor_sync(0xffffffffu, m, o));
        if (tid == 0) redS[0] = m;
    }
    __syncthreads();
    const float M = redS[0];
    float e = (tid < LL) ? expf(logit - M) : 0.f;
    {
        float s = e;
        #pragma unroll
        for (int o = 16; o; o >>= 1) s += __shfl_xor_sync(0xffffffffu, s, o);
        if ((tid & 31) == 0) redS[8 + (tid >> 5)] = s;
    }
    __syncthreads();
    if (tid < 32) {
        float s = (tid < 8) ? redS[8 + tid] : 0.f;
        #pragma unroll
        for (int o = 4; o; o >>= 1) s += __shfl_xor_sync(0xffffffffu, s, o);
        if (tid == 0) redS[16] = s;
    }
    __syncthreads();
    const float S = redS[16];
    if (tid < LL) {
        float a = e / S;
        attnS[tid] = a;
        out[(size_t)BB * DD + (size_t)b * LL + tid] = a;
    }
    __syncthreads();

    // ---- user_interest[b][d] = sum_l attn[l] * hist[b][l][d] ----
    if (tid < DD) {
        float s = 0.f;
        #pragma unroll 4
        for (int l = 0; l < LL; ++l)
            s = fmaf(attnS[l], histS[l * 129 + tid], s);
        out[(size_t)b * DD + tid] = s;
    }
}

extern "C" void kernel_launch(void* const* d_in, const int* in_sizes, int n_in,
                              void* d_out, int out_size)
{
    const float* hist = (const float*)d_in[0];
    const float* tgt  = (const float*)d_in[1];
    const int*   mask = (const int*)  d_in[2];
    const float* W0   = (const float*)d_in[3];
    const float* b0   = (const float*)d_in[4];
    const float* W1   = (const float*)d_in[5];
    const float* b1   = (const float*)d_in[6];
    const float* W2   = (const float*)d_in[7];
    const float* b2   = (const float*)d_in[8];
    float* out = (float*)d_out;

    static int smem_set = 0;
    const int smem_bytes = SMEM_FLOATS * (int)sizeof(float);
    if (!smem_set) {
        cudaFuncSetAttribute(din_kernel,
                             cudaFuncAttributeMaxDynamicSharedMemorySize,
                             smem_bytes);
        smem_set = 1;
    }
    din_kernel<<<BB, 256, smem_bytes>>>(hist, tgt, mask, W0, b0, W1, b1, W2, b2, out);
}